// round 1
// baseline (speedup 1.0000x reference)
#include <cuda_runtime.h>
#include <math.h>

// Problem constants
#define B 2
#define S 2048
#define D 1024
#define H 16
#define HD 64
#define MASK_VALUE -1000000.0f

// Scratch (static device globals — no allocation allowed)
__device__ float g_q[B * S * D];
__device__ float g_k[B * S * D];
__device__ float g_v[B * S * D];
__device__ float g_attn[B * S * D];

// ---------------------------------------------------------------------------
// GEMM: C[M,N] = A[M,K] @ W[K,N], all row-major fp32.
// 128x128 block tile, BK=16, 256 threads, 8x8 register tile per thread.
// ---------------------------------------------------------------------------
__global__ __launch_bounds__(256) void gemm_kernel(
    const float* __restrict__ A, const float* __restrict__ W,
    float* __restrict__ C, int M, int N, int K)
{
    __shared__ float As[16][132];  // transposed A tile, padded vs bank conflicts
    __shared__ float Bs[16][128];

    const int tid = threadIdx.x;
    const int tx = tid & 15;       // 0..15
    const int ty = tid >> 4;       // 0..15
    const int bm = blockIdx.y * 128;
    const int bn = blockIdx.x * 128;

    float acc[8][8];
#pragma unroll
    for (int i = 0; i < 8; i++)
#pragma unroll
        for (int j = 0; j < 8; j++) acc[i][j] = 0.f;

    const float* Aptr = A + (size_t)bm * K;
    const float* Bptr = W + bn;

    for (int k0 = 0; k0 < K; k0 += 16) {
        // Load A tile 128x16 (2 float4 per thread), store transposed
#pragma unroll
        for (int i = 0; i < 2; i++) {
            int idx = tid * 2 + i;          // 0..511
            int row = idx >> 2;             // 0..127
            int c4  = idx & 3;              // 0..3
            float4 va = *(const float4*)(Aptr + (size_t)row * K + k0 + c4 * 4);
            As[c4 * 4 + 0][row] = va.x;
            As[c4 * 4 + 1][row] = va.y;
            As[c4 * 4 + 2][row] = va.z;
            As[c4 * 4 + 3][row] = va.w;
        }
        // Load B tile 16x128 (2 float4 per thread)
#pragma unroll
        for (int i = 0; i < 2; i++) {
            int idx = tid * 2 + i;          // 0..511
            int row = idx >> 5;             // 0..15
            int c4  = idx & 31;             // 0..31
            *(float4*)(&Bs[row][c4 * 4]) =
                *(const float4*)(Bptr + (size_t)(k0 + row) * N + c4 * 4);
        }
        __syncthreads();

#pragma unroll
        for (int k = 0; k < 16; k++) {
            float a[8], b[8];
#pragma unroll
            for (int i = 0; i < 8; i++) a[i] = As[k][ty * 8 + i];
#pragma unroll
            for (int j = 0; j < 8; j++) b[j] = Bs[k][tx * 8 + j];
#pragma unroll
            for (int i = 0; i < 8; i++)
#pragma unroll
                for (int j = 0; j < 8; j++)
                    acc[i][j] = fmaf(a[i], b[j], acc[i][j]);
        }
        __syncthreads();
    }

#pragma unroll
    for (int i = 0; i < 8; i++) {
        int r = bm + ty * 8 + i;
#pragma unroll
        for (int j = 0; j < 8; j += 4) {
            *(float4*)(&C[(size_t)r * N + bn + tx * 8 + j]) =
                make_float4(acc[i][j], acc[i][j + 1], acc[i][j + 2], acc[i][j + 3]);
        }
    }
}

// ---------------------------------------------------------------------------
// Flash-style attention. One CTA = 64 query rows of one (b,h).
// Online softmax with finite MASK_VALUE (handles valid_len==0 -> uniform).
// 256 threads as 16x16; each thread owns a 4x4 fragment of S and of O.
// ---------------------------------------------------------------------------
#define ATTN_SMEM_FLOATS (4 * 64 * 65 + 3 * 64)
#define ATTN_SMEM_BYTES (ATTN_SMEM_FLOATS * 4)

__global__ __launch_bounds__(256) void attn_kernel(
    const float* __restrict__ q, const float* __restrict__ k,
    const float* __restrict__ v, const int* __restrict__ valid,
    float* __restrict__ out)
{
    extern __shared__ float sm[];
    float* Qs   = sm;                 // [64][65]
    float* Ks   = Qs + 64 * 65;       // [64][65]
    float* Vs   = Ks + 64 * 65;       // [64][65]
    float* Pt   = Vs + 64 * 65;       // [64][65]
    float* mrow = Pt + 64 * 65;       // [64]
    float* lrow = mrow + 64;          // [64]
    float* arow = lrow + 64;          // [64]

    const int tid = threadIdx.x;
    const int tx = tid & 15;          // column group (dims / key cols)
    const int ty = tid >> 4;          // row group (query rows)
    const int bh = blockIdx.y;
    const int b  = bh / H;
    const int h  = bh % H;
    const int q0 = blockIdx.x * 64;
    const int vlen = valid[b];
    const float scale = 0.125f;       // 1/sqrt(HD)

    const float* qbase = q + (size_t)b * S * D + (size_t)h * HD;
    const float* kbase = k + (size_t)b * S * D + (size_t)h * HD;
    const float* vbase = v + (size_t)b * S * D + (size_t)h * HD;

    // Load Q tile [64][64] (1024 float4 total, 4 per thread)
#pragma unroll
    for (int i = 0; i < 4; i++) {
        int idx = tid + i * 256;
        int row = idx >> 4;
        int c4  = idx & 15;
        float4 t = *(const float4*)(qbase + (size_t)(q0 + row) * D + c4 * 4);
        Qs[row * 65 + c4 * 4 + 0] = t.x;
        Qs[row * 65 + c4 * 4 + 1] = t.y;
        Qs[row * 65 + c4 * 4 + 2] = t.z;
        Qs[row * 65 + c4 * 4 + 3] = t.w;
    }
    if (tid < 64) {
        mrow[tid] = -INFINITY;
        lrow[tid] = 0.f;
    }

    float accO[4][4];
#pragma unroll
    for (int i = 0; i < 4; i++)
#pragma unroll
        for (int j = 0; j < 4; j++) accO[i][j] = 0.f;

    __syncthreads();

    for (int kt = 0; kt < S / 64; kt++) {
        const int kr0 = kt * 64;
        // Load K and V tiles
#pragma unroll
        for (int i = 0; i < 4; i++) {
            int idx = tid + i * 256;
            int row = idx >> 4;
            int c4  = idx & 15;
            float4 tk = *(const float4*)(kbase + (size_t)(kr0 + row) * D + c4 * 4);
            float4 tv = *(const float4*)(vbase + (size_t)(kr0 + row) * D + c4 * 4);
            Ks[row * 65 + c4 * 4 + 0] = tk.x;
            Ks[row * 65 + c4 * 4 + 1] = tk.y;
            Ks[row * 65 + c4 * 4 + 2] = tk.z;
            Ks[row * 65 + c4 * 4 + 3] = tk.w;
            Vs[row * 65 + c4 * 4 + 0] = tv.x;
            Vs[row * 65 + c4 * 4 + 1] = tv.y;
            Vs[row * 65 + c4 * 4 + 2] = tv.z;
            Vs[row * 65 + c4 * 4 + 3] = tv.w;
        }
        __syncthreads();

        // Scores: S = Q @ K^T  (64x64x64)
        float acc[4][4];
#pragma unroll
        for (int i = 0; i < 4; i++)
#pragma unroll
            for (int j = 0; j < 4; j++) acc[i][j] = 0.f;

#pragma unroll 8
        for (int kk = 0; kk < 64; kk++) {
            float a[4], bb[4];
#pragma unroll
            for (int i = 0; i < 4; i++) a[i] = Qs[(ty * 4 + i) * 65 + kk];
#pragma unroll
            for (int j = 0; j < 4; j++) bb[j] = Ks[(tx * 4 + j) * 65 + kk];
#pragma unroll
            for (int i = 0; i < 4; i++)
#pragma unroll
                for (int j = 0; j < 4; j++)
                    acc[i][j] = fmaf(a[i], bb[j], acc[i][j]);
        }

        // Scale + mask, write to Pt
#pragma unroll
        for (int j = 0; j < 4; j++) {
            int kc = kr0 + tx * 4 + j;
            bool m = (kc < vlen);
#pragma unroll
            for (int i = 0; i < 4; i++) {
                float sv = m ? acc[i][j] * scale : MASK_VALUE;
                Pt[(ty * 4 + i) * 65 + tx * 4 + j] = sv;
            }
        }
        __syncthreads();

        // Online softmax per row (threads 0..63, one row each)
        if (tid < 64) {
            const int r = tid;
            float mprev = mrow[r];
            float newm = mprev;
#pragma unroll 8
            for (int c = 0; c < 64; c++) newm = fmaxf(newm, Pt[r * 65 + c]);
            float alpha = __expf(mprev - newm);  // exp(-inf)=0 on first tile
            float sum = 0.f;
#pragma unroll 8
            for (int c = 0; c < 64; c++) {
                float p = __expf(Pt[r * 65 + c] - newm);
                Pt[r * 65 + c] = p;
                sum += p;
            }
            lrow[r] = lrow[r] * alpha + sum;
            mrow[r] = newm;
            arow[r] = alpha;
        }
        __syncthreads();

        // O = O*alpha + P @ V
        float al[4];
#pragma unroll
        for (int i = 0; i < 4; i++) al[i] = arow[ty * 4 + i];
#pragma unroll
        for (int i = 0; i < 4; i++)
#pragma unroll
            for (int j = 0; j < 4; j++) accO[i][j] *= al[i];

#pragma unroll 8
        for (int kk = 0; kk < 64; kk++) {
            float p[4], vv[4];
#pragma unroll
            for (int i = 0; i < 4; i++) p[i] = Pt[(ty * 4 + i) * 65 + kk];
#pragma unroll
            for (int j = 0; j < 4; j++) vv[j] = Vs[kk * 65 + tx * 4 + j];
#pragma unroll
            for (int i = 0; i < 4; i++)
#pragma unroll
                for (int j = 0; j < 4; j++)
                    accO[i][j] = fmaf(p[i], vv[j], accO[i][j]);
        }
        __syncthreads();  // before next tile overwrites Ks/Vs/Pt
    }

    // Epilogue: divide by l, write to [B,S,D] with head offset
    float linv[4];
#pragma unroll
    for (int i = 0; i < 4; i++) linv[i] = 1.f / lrow[ty * 4 + i];
#pragma unroll
    for (int i = 0; i < 4; i++) {
        int r = q0 + ty * 4 + i;
#pragma unroll
        for (int j = 0; j < 4; j++) {
            out[((size_t)b * S + r) * D + h * HD + tx * 4 + j] = accO[i][j] * linv[i];
        }
    }
}

// ---------------------------------------------------------------------------
// Launch
// ---------------------------------------------------------------------------
extern "C" void kernel_launch(void* const* d_in, const int* in_sizes, int n_in,
                              void* d_out, int out_size)
{
    const float* Q  = (const float*)d_in[0];
    const float* K  = (const float*)d_in[1];
    const float* V  = (const float*)d_in[2];
    const int* valid = (const int*)d_in[3];
    const float* Wq = (const float*)d_in[4];
    const float* Wk = (const float*)d_in[5];
    const float* Wv = (const float*)d_in[6];
    const float* Wo = (const float*)d_in[7];
    float* out = (float*)d_out;

    float *gq, *gk, *gv, *ga;
    cudaGetSymbolAddress((void**)&gq, g_q);
    cudaGetSymbolAddress((void**)&gk, g_k);
    cudaGetSymbolAddress((void**)&gv, g_v);
    cudaGetSymbolAddress((void**)&ga, g_attn);

    cudaFuncSetAttribute(attn_kernel, cudaFuncAttributeMaxDynamicSharedMemorySize,
                         ATTN_SMEM_BYTES);

    dim3 ggrid(D / 128, (B * S) / 128);  // (8, 32)
    gemm_kernel<<<ggrid, 256>>>(Q, Wq, gq, B * S, D, D);
    gemm_kernel<<<ggrid, 256>>>(K, Wk, gk, B * S, D, D);
    gemm_kernel<<<ggrid, 256>>>(V, Wv, gv, B * S, D, D);

    dim3 agrid(S / 64, B * H);           // (32, 32)
    attn_kernel<<<agrid, 256, ATTN_SMEM_BYTES>>>(gq, gk, gv, valid, ga);

    gemm_kernel<<<ggrid, 256>>>(ga, Wo, out, B * S, D, D);
}

// round 4
// speedup vs baseline: 2.3728x; 2.3728x over previous
#include <cuda_runtime.h>
#include <math.h>
#include <stdint.h>

// Problem constants
#define B 2
#define S 2048
#define D 1024
#define H 16
#define HD 64
#define MASK_VALUE -1000000.0f

// Scratch (static device globals — no allocation allowed)
__device__ float g_q[B * S * D];
__device__ float g_k[B * S * D];
__device__ float g_v[B * S * D];
__device__ float g_attn[B * S * D];
__device__ float g_wt[4][D * D];   // transposed weights ([N][K] = col-major B)

// ===========================================================================
// Helpers
// ===========================================================================
static __device__ __forceinline__ uint32_t smem_u32(const void* p) {
    uint32_t a;
    asm("{ .reg .u64 t; cvta.to.shared.u64 t, %1; cvt.u32.u64 %0, t; }"
        : "=r"(a) : "l"(p));
    return a;
}
static __device__ __forceinline__ uint32_t f2tf32(float x) {
    uint32_t r;
    asm("cvt.rna.tf32.f32 %0, %1;" : "=r"(r) : "f"(x));
    return r;
}
static __device__ __forceinline__ void cp_async16(uint32_t smem, const void* gmem) {
    asm volatile("cp.async.ca.shared.global [%0], [%1], 16;"
                 :: "r"(smem), "l"(gmem) : "memory");
}
static __device__ __forceinline__ void cp_commit() {
    asm volatile("cp.async.commit_group;" ::: "memory");
}
static __device__ __forceinline__ void mma_tf32(
    float d[4], const uint32_t a[4], uint32_t b0, uint32_t b1)
{
    asm volatile(
        "mma.sync.aligned.m16n8k8.row.col.f32.tf32.tf32.f32 "
        "{%0,%1,%2,%3}, {%4,%5,%6,%7}, {%8,%9}, {%0,%1,%2,%3};"
        : "+f"(d[0]), "+f"(d[1]), "+f"(d[2]), "+f"(d[3])
        : "r"(a[0]), "r"(a[1]), "r"(a[2]), "r"(a[3]), "r"(b0), "r"(b1));
}

// ===========================================================================
// Weight transpose: Wt[n*D + k] = W[k*D + n]   (D x D)
// ===========================================================================
__global__ __launch_bounds__(256) void transpose_kernel(
    const float* __restrict__ W, float* __restrict__ Wt)
{
    __shared__ float t[32][33];
    int x = blockIdx.x * 32 + threadIdx.x;
    int y = blockIdx.y * 32 + threadIdx.y;
#pragma unroll
    for (int i = 0; i < 32; i += 8)
        t[threadIdx.y + i][threadIdx.x] = W[(size_t)(y + i) * D + x];
    __syncthreads();
    x = blockIdx.y * 32 + threadIdx.x;
    y = blockIdx.x * 32 + threadIdx.y;
#pragma unroll
    for (int i = 0; i < 32; i += 8)
        Wt[(size_t)(y + i) * D + x] = t[threadIdx.x][threadIdx.y + i];
}

// ===========================================================================
// tf32 mma.sync GEMM: C[M,N] = A[M,K] @ Bt[N,K]^T   (M=4096, N=K=1024)
// 128x128 CTA tile, BK=32, 256 threads (8 warps, warp tile 32Mx64N),
// cp.async double-buffered SMEM.
// ===========================================================================
#define BK 32
#define NKCHUNK (D / BK)           // 32
#define APITCH 36                  // floats per SMEM row (pad 4 vs conflicts)
#define TILE_F (128 * APITCH)      // floats per tile buffer
#define GEMM_SMEM_BYTES (4 * TILE_F * 4)   // 73728

static __device__ __forceinline__ void gemm_load_tile(
    uint32_t sA, uint32_t sB, const float* Ab, const float* Bb, int kc, int tid)
{
#pragma unroll
    for (int t = 0; t < 4; t++) {
        int idx = tid + (t << 8);       // 0..1023
        int row = idx >> 3;             // 0..127
        int c   = idx & 7;              // float4 column 0..7
        const float* ga = Ab + (size_t)row * D + kc * BK + c * 4;
        const float* gb = Bb + (size_t)row * D + kc * BK + c * 4;
        uint32_t off = (uint32_t)(row * APITCH + c * 4) * 4;
        cp_async16(sA + off, ga);
        cp_async16(sB + off, gb);
    }
}

__global__ __launch_bounds__(256) void gemm_tf32(
    const float* __restrict__ A, const float* __restrict__ Bt,
    float* __restrict__ C)
{
    extern __shared__ float smf[];
    float* bufA[2] = { smf,            smf + TILE_F };
    float* bufB[2] = { smf + 2 * TILE_F, smf + 3 * TILE_F };
    uint32_t uA[2] = { smem_u32(bufA[0]), smem_u32(bufA[1]) };
    uint32_t uB[2] = { smem_u32(bufB[0]), smem_u32(bufB[1]) };

    const int tid = threadIdx.x;
    const int wid = tid >> 5;
    const int lane = tid & 31;
    const int g  = lane >> 2;     // group 0..7
    const int tg = lane & 3;      // thread-in-group 0..3
    const int wm = wid & 3;       // warp M index (0..3) -> 32 rows each
    const int wn = wid >> 2;      // warp N index (0..1) -> 64 cols each

    const int bm = blockIdx.y * 128;
    const int bn = blockIdx.x * 128;
    const float* Ab = A  + (size_t)bm * D;
    const float* Bb = Bt + (size_t)bn * D;

    float d[2][8][4];
#pragma unroll
    for (int mi = 0; mi < 2; mi++)
#pragma unroll
        for (int ni = 0; ni < 8; ni++)
#pragma unroll
            for (int r = 0; r < 4; r++) d[mi][ni][r] = 0.f;

    gemm_load_tile(uA[0], uB[0], Ab, Bb, 0, tid);
    cp_commit();

    for (int kc = 0; kc < NKCHUNK; kc++) {
        const int buf = kc & 1;
        if (kc + 1 < NKCHUNK) {
            gemm_load_tile(uA[buf ^ 1], uB[buf ^ 1], Ab, Bb, kc + 1, tid);
            cp_commit();
            asm volatile("cp.async.wait_group 1;" ::: "memory");
        } else {
            asm volatile("cp.async.wait_group 0;" ::: "memory");
        }
        __syncthreads();

        const float* As = bufA[buf];
        const float* Bs = bufB[buf];
#pragma unroll
        for (int ks = 0; ks < 4; ks++) {
            const int k0 = ks * 8;
            uint32_t af[2][4];
#pragma unroll
            for (int mi = 0; mi < 2; mi++) {
                int r = wm * 32 + mi * 16 + g;
                af[mi][0] = f2tf32(As[r * APITCH + k0 + tg]);
                af[mi][1] = f2tf32(As[(r + 8) * APITCH + k0 + tg]);
                af[mi][2] = f2tf32(As[r * APITCH + k0 + tg + 4]);
                af[mi][3] = f2tf32(As[(r + 8) * APITCH + k0 + tg + 4]);
            }
#pragma unroll
            for (int ni = 0; ni < 8; ni++) {
                int r = wn * 64 + ni * 8 + g;
                uint32_t b0 = f2tf32(Bs[r * APITCH + k0 + tg]);
                uint32_t b1 = f2tf32(Bs[r * APITCH + k0 + tg + 4]);
#pragma unroll
                for (int mi = 0; mi < 2; mi++)
                    mma_tf32(d[mi][ni], af[mi], b0, b1);
            }
        }
        __syncthreads();
    }

    // Epilogue: c0,c1 -> (row, 2tg..2tg+1); c2,c3 -> (row+8, same cols)
#pragma unroll
    for (int mi = 0; mi < 2; mi++) {
        int row = bm + wm * 32 + mi * 16 + g;
#pragma unroll
        for (int ni = 0; ni < 8; ni++) {
            int col = bn + wn * 64 + ni * 8 + tg * 2;
            *(float2*)(&C[(size_t)row * D + col]) =
                make_float2(d[mi][ni][0], d[mi][ni][1]);
            *(float2*)(&C[(size_t)(row + 8) * D + col]) =
                make_float2(d[mi][ni][2], d[mi][ni][3]);
        }
    }
}

// ===========================================================================
// Flash-style SIMT attention with masked-tile skipping.
// MASK_VALUE=-1e6 underflows exp() to exactly 0 and never raises the row max,
// so tiles with kr0 >= vlen contribute nothing (vlen==0 processes all tiles ->
// uniform softmax, matching the reference).
// ===========================================================================
#define ATTN_SMEM_FLOATS (4 * 64 * 65 + 3 * 64)
#define ATTN_SMEM_BYTES (ATTN_SMEM_FLOATS * 4)

__global__ __launch_bounds__(256) void attn_kernel(
    const float* __restrict__ q, const float* __restrict__ k,
    const float* __restrict__ v, const int* __restrict__ valid,
    float* __restrict__ out)
{
    extern __shared__ float sm[];
    float* Qs   = sm;
    float* Ks   = Qs + 64 * 65;
    float* Vs   = Ks + 64 * 65;
    float* Pt   = Vs + 64 * 65;
    float* mrow = Pt + 64 * 65;
    float* lrow = mrow + 64;
    float* arow = lrow + 64;

    const int tid = threadIdx.x;
    const int tx = tid & 15;
    const int ty = tid >> 4;
    const int bh = blockIdx.y;
    const int b  = bh / H;
    const int h  = bh % H;
    const int q0 = blockIdx.x * 64;
    const int vlen = valid[b];
    const float scale = 0.125f;

    const float* qbase = q + (size_t)b * S * D + (size_t)h * HD;
    const float* kbase = k + (size_t)b * S * D + (size_t)h * HD;
    const float* vbase = v + (size_t)b * S * D + (size_t)h * HD;

#pragma unroll
    for (int i = 0; i < 4; i++) {
        int idx = tid + i * 256;
        int row = idx >> 4;
        int c4  = idx & 15;
        float4 t = *(const float4*)(qbase + (size_t)(q0 + row) * D + c4 * 4);
        Qs[row * 65 + c4 * 4 + 0] = t.x;
        Qs[row * 65 + c4 * 4 + 1] = t.y;
        Qs[row * 65 + c4 * 4 + 2] = t.z;
        Qs[row * 65 + c4 * 4 + 3] = t.w;
    }
    if (tid < 64) {
        mrow[tid] = -INFINITY;
        lrow[tid] = 0.f;
    }

    float accO[4][4];
#pragma unroll
    for (int i = 0; i < 4; i++)
#pragma unroll
        for (int j = 0; j < 4; j++) accO[i][j] = 0.f;

    __syncthreads();

    const int nk = (vlen == 0) ? (S / 64) : ((vlen + 63) >> 6);

    for (int kt = 0; kt < nk; kt++) {
        const int kr0 = kt * 64;
#pragma unroll
        for (int i = 0; i < 4; i++) {
            int idx = tid + i * 256;
            int row = idx >> 4;
            int c4  = idx & 15;
            float4 tk = *(const float4*)(kbase + (size_t)(kr0 + row) * D + c4 * 4);
            float4 tv = *(const float4*)(vbase + (size_t)(kr0 + row) * D + c4 * 4);
            Ks[row * 65 + c4 * 4 + 0] = tk.x;
            Ks[row * 65 + c4 * 4 + 1] = tk.y;
            Ks[row * 65 + c4 * 4 + 2] = tk.z;
            Ks[row * 65 + c4 * 4 + 3] = tk.w;
            Vs[row * 65 + c4 * 4 + 0] = tv.x;
            Vs[row * 65 + c4 * 4 + 1] = tv.y;
            Vs[row * 65 + c4 * 4 + 2] = tv.z;
            Vs[row * 65 + c4 * 4 + 3] = tv.w;
        }
        __syncthreads();

        float acc[4][4];
#pragma unroll
        for (int i = 0; i < 4; i++)
#pragma unroll
            for (int j = 0; j < 4; j++) acc[i][j] = 0.f;

#pragma unroll 8
        for (int kk = 0; kk < 64; kk++) {
            float a[4], bb[4];
#pragma unroll
            for (int i = 0; i < 4; i++) a[i] = Qs[(ty * 4 + i) * 65 + kk];
#pragma unroll
            for (int j = 0; j < 4; j++) bb[j] = Ks[(tx * 4 + j) * 65 + kk];
#pragma unroll
            for (int i = 0; i < 4; i++)
#pragma unroll
                for (int j = 0; j < 4; j++)
                    acc[i][j] = fmaf(a[i], bb[j], acc[i][j]);
        }

#pragma unroll
        for (int j = 0; j < 4; j++) {
            int kc = kr0 + tx * 4 + j;
            bool m = (kc < vlen);
#pragma unroll
            for (int i = 0; i < 4; i++) {
                float sv = m ? acc[i][j] * scale : MASK_VALUE;
                Pt[(ty * 4 + i) * 65 + tx * 4 + j] = sv;
            }
        }
        __syncthreads();

        if (tid < 64) {
            const int r = tid;
            float mprev = mrow[r];
            float newm = mprev;
#pragma unroll 8
            for (int c = 0; c < 64; c++) newm = fmaxf(newm, Pt[r * 65 + c]);
            float alpha = __expf(mprev - newm);
            float sum = 0.f;
#pragma unroll 8
            for (int c = 0; c < 64; c++) {
                float p = __expf(Pt[r * 65 + c] - newm);
                Pt[r * 65 + c] = p;
                sum += p;
            }
            lrow[r] = lrow[r] * alpha + sum;
            mrow[r] = newm;
            arow[r] = alpha;
        }
        __syncthreads();

        float al[4];
#pragma unroll
        for (int i = 0; i < 4; i++) al[i] = arow[ty * 4 + i];
#pragma unroll
        for (int i = 0; i < 4; i++)
#pragma unroll
            for (int j = 0; j < 4; j++) accO[i][j] *= al[i];

#pragma unroll 8
        for (int kk = 0; kk < 64; kk++) {
            float p[4], vv[4];
#pragma unroll
            for (int i = 0; i < 4; i++) p[i] = Pt[(ty * 4 + i) * 65 + kk];
#pragma unroll
            for (int j = 0; j < 4; j++) vv[j] = Vs[kk * 65 + tx * 4 + j];
#pragma unroll
            for (int i = 0; i < 4; i++)
#pragma unroll
                for (int j = 0; j < 4; j++)
                    accO[i][j] = fmaf(p[i], vv[j], accO[i][j]);
        }
        __syncthreads();
    }

    float linv[4];
#pragma unroll
    for (int i = 0; i < 4; i++) linv[i] = 1.f / lrow[ty * 4 + i];
#pragma unroll
    for (int i = 0; i < 4; i++) {
        int r = q0 + ty * 4 + i;
#pragma unroll
        for (int j = 0; j < 4; j++) {
            out[((size_t)b * S + r) * D + h * HD + tx * 4 + j] = accO[i][j] * linv[i];
        }
    }
}

// ===========================================================================
// Launch
// ===========================================================================
extern "C" void kernel_launch(void* const* d_in, const int* in_sizes, int n_in,
                              void* d_out, int out_size)
{
    const float* Q  = (const float*)d_in[0];
    const float* K  = (const float*)d_in[1];
    const float* V  = (const float*)d_in[2];
    const int* valid = (const int*)d_in[3];
    const float* Wq = (const float*)d_in[4];
    const float* Wk = (const float*)d_in[5];
    const float* Wv = (const float*)d_in[6];
    const float* Wo = (const float*)d_in[7];
    float* out = (float*)d_out;

    float *gq, *gk, *gv, *ga, *gwt;
    cudaGetSymbolAddress((void**)&gq, g_q);
    cudaGetSymbolAddress((void**)&gk, g_k);
    cudaGetSymbolAddress((void**)&gv, g_v);
    cudaGetSymbolAddress((void**)&ga, g_attn);
    cudaGetSymbolAddress((void**)&gwt, g_wt);
    float* wtq = gwt;
    float* wtk = gwt + (size_t)D * D;
    float* wtv = gwt + (size_t)2 * D * D;
    float* wto = gwt + (size_t)3 * D * D;

    cudaFuncSetAttribute(attn_kernel, cudaFuncAttributeMaxDynamicSharedMemorySize,
                         ATTN_SMEM_BYTES);
    cudaFuncSetAttribute(gemm_tf32, cudaFuncAttributeMaxDynamicSharedMemorySize,
                         GEMM_SMEM_BYTES);

    dim3 tgrid(32, 32), tblk(32, 8);
    transpose_kernel<<<tgrid, tblk>>>(Wq, wtq);
    transpose_kernel<<<tgrid, tblk>>>(Wk, wtk);
    transpose_kernel<<<tgrid, tblk>>>(Wv, wtv);
    transpose_kernel<<<tgrid, tblk>>>(Wo, wto);

    dim3 ggrid(D / 128, (B * S) / 128);  // (8, 32)
    gemm_tf32<<<ggrid, 256, GEMM_SMEM_BYTES>>>(Q, wtq, gq);
    gemm_tf32<<<ggrid, 256, GEMM_SMEM_BYTES>>>(K, wtk, gk);
    gemm_tf32<<<ggrid, 256, GEMM_SMEM_BYTES>>>(V, wtv, gv);

    dim3 agrid(S / 64, B * H);           // (32, 32)
    attn_kernel<<<agrid, 256, ATTN_SMEM_BYTES>>>(gq, gk, gv, valid, ga);

    gemm_tf32<<<ggrid, 256, GEMM_SMEM_BYTES>>>(ga, wto, out);
}

// round 7
// speedup vs baseline: 3.9574x; 1.6678x over previous
#include <cuda_runtime.h>
#include <math.h>
#include <stdint.h>

// Problem constants
#define B 2
#define S 2048
#define D 1024
#define H 16
#define HD 64
#define MASK_VALUE -1000000.0f

// Scratch (static device globals — no allocation allowed)
__device__ float g_q[B * S * D];
__device__ float g_k[B * S * D];
__device__ float g_v[B * S * D];
__device__ float g_attn[B * S * D];
__device__ float g_wt[4][D * D];   // transposed weights ([N][K] = col-major B)

// ===========================================================================
// Helpers
// ===========================================================================
static __device__ __forceinline__ uint32_t smem_u32(const void* p) {
    uint32_t a;
    asm("{ .reg .u64 t; cvta.to.shared.u64 t, %1; cvt.u32.u64 %0, t; }"
        : "=r"(a) : "l"(p));
    return a;
}
static __device__ __forceinline__ uint32_t f2tf32(float x) {
    uint32_t r;
    asm("cvt.rna.tf32.f32 %0, %1;" : "=r"(r) : "f"(x));
    return r;
}
static __device__ __forceinline__ void cp_async16(uint32_t smem, const void* gmem) {
    asm volatile("cp.async.ca.shared.global [%0], [%1], 16;"
                 :: "r"(smem), "l"(gmem) : "memory");
}
static __device__ __forceinline__ void cp_commit() {
    asm volatile("cp.async.commit_group;" ::: "memory");
}
static __device__ __forceinline__ void mma_tf32(
    float d[4], const uint32_t a[4], uint32_t b0, uint32_t b1)
{
    asm volatile(
        "mma.sync.aligned.m16n8k8.row.col.f32.tf32.tf32.f32 "
        "{%0,%1,%2,%3}, {%4,%5,%6,%7}, {%8,%9}, {%0,%1,%2,%3};"
        : "+f"(d[0]), "+f"(d[1]), "+f"(d[2]), "+f"(d[3])
        : "r"(a[0]), "r"(a[1]), "r"(a[2]), "r"(a[3]), "r"(b0), "r"(b1));
}

// ===========================================================================
// Weight transpose: Wt[n*D + k] = W[k*D + n]   (D x D)
// ===========================================================================
__global__ __launch_bounds__(256) void transpose_kernel(
    const float* __restrict__ W, float* __restrict__ Wt)
{
    __shared__ float t[32][33];
    int x = blockIdx.x * 32 + threadIdx.x;
    int y = blockIdx.y * 32 + threadIdx.y;
#pragma unroll
    for (int i = 0; i < 32; i += 8)
        t[threadIdx.y + i][threadIdx.x] = W[(size_t)(y + i) * D + x];
    __syncthreads();
    x = blockIdx.y * 32 + threadIdx.x;
    y = blockIdx.x * 32 + threadIdx.y;
#pragma unroll
    for (int i = 0; i < 32; i += 8)
        Wt[(size_t)(y + i) * D + x] = t[threadIdx.x][threadIdx.y + i];
}

// ===========================================================================
// tf32 mma.sync GEMM: C[M,N] = A[M,K] @ Bt[N,K]^T   (M=4096, N=K=1024)
// 128x128 CTA tile, BK=32, 256 threads (8 warps, warp tile 32Mx64N),
// cp.async double-buffered SMEM.
// ===========================================================================
#define BK 32
#define NKCHUNK (D / BK)           // 32
#define APITCH 36                  // floats per SMEM row (pad 4 vs conflicts)
#define TILE_F (128 * APITCH)      // floats per tile buffer
#define GEMM_SMEM_BYTES (4 * TILE_F * 4)   // 73728

static __device__ __forceinline__ void gemm_load_tile(
    uint32_t sA, uint32_t sB, const float* Ab, const float* Bb, int kc, int tid)
{
#pragma unroll
    for (int t = 0; t < 4; t++) {
        int idx = tid + (t << 8);       // 0..1023
        int row = idx >> 3;             // 0..127
        int c   = idx & 7;              // float4 column 0..7
        const float* ga = Ab + (size_t)row * D + kc * BK + c * 4;
        const float* gb = Bb + (size_t)row * D + kc * BK + c * 4;
        uint32_t off = (uint32_t)(row * APITCH + c * 4) * 4;
        cp_async16(sA + off, ga);
        cp_async16(sB + off, gb);
    }
}

__global__ __launch_bounds__(256) void gemm_tf32(
    const float* __restrict__ A, const float* __restrict__ Bt,
    float* __restrict__ C)
{
    extern __shared__ float smf[];
    float* bufA[2] = { smf,            smf + TILE_F };
    float* bufB[2] = { smf + 2 * TILE_F, smf + 3 * TILE_F };
    uint32_t uA[2] = { smem_u32(bufA[0]), smem_u32(bufA[1]) };
    uint32_t uB[2] = { smem_u32(bufB[0]), smem_u32(bufB[1]) };

    const int tid = threadIdx.x;
    const int wid = tid >> 5;
    const int lane = tid & 31;
    const int g  = lane >> 2;
    const int tg = lane & 3;
    const int wm = wid & 3;
    const int wn = wid >> 2;

    const int bm = blockIdx.y * 128;
    const int bn = blockIdx.x * 128;
    const float* Ab = A  + (size_t)bm * D;
    const float* Bb = Bt + (size_t)bn * D;

    float d[2][8][4];
#pragma unroll
    for (int mi = 0; mi < 2; mi++)
#pragma unroll
        for (int ni = 0; ni < 8; ni++)
#pragma unroll
            for (int r = 0; r < 4; r++) d[mi][ni][r] = 0.f;

    gemm_load_tile(uA[0], uB[0], Ab, Bb, 0, tid);
    cp_commit();

    for (int kc = 0; kc < NKCHUNK; kc++) {
        const int buf = kc & 1;
        if (kc + 1 < NKCHUNK) {
            gemm_load_tile(uA[buf ^ 1], uB[buf ^ 1], Ab, Bb, kc + 1, tid);
            cp_commit();
            asm volatile("cp.async.wait_group 1;" ::: "memory");
        } else {
            asm volatile("cp.async.wait_group 0;" ::: "memory");
        }
        __syncthreads();

        const float* As = bufA[buf];
        const float* Bs = bufB[buf];
#pragma unroll
        for (int ks = 0; ks < 4; ks++) {
            const int k0 = ks * 8;
            uint32_t af[2][4];
#pragma unroll
            for (int mi = 0; mi < 2; mi++) {
                int r = wm * 32 + mi * 16 + g;
                af[mi][0] = f2tf32(As[r * APITCH + k0 + tg]);
                af[mi][1] = f2tf32(As[(r + 8) * APITCH + k0 + tg]);
                af[mi][2] = f2tf32(As[r * APITCH + k0 + tg + 4]);
                af[mi][3] = f2tf32(As[(r + 8) * APITCH + k0 + tg + 4]);
            }
#pragma unroll
            for (int ni = 0; ni < 8; ni++) {
                int r = wn * 64 + ni * 8 + g;
                uint32_t b0 = f2tf32(Bs[r * APITCH + k0 + tg]);
                uint32_t b1 = f2tf32(Bs[r * APITCH + k0 + tg + 4]);
#pragma unroll
                for (int mi = 0; mi < 2; mi++)
                    mma_tf32(d[mi][ni], af[mi], b0, b1);
            }
        }
        __syncthreads();
    }

#pragma unroll
    for (int mi = 0; mi < 2; mi++) {
        int row = bm + wm * 32 + mi * 16 + g;
#pragma unroll
        for (int ni = 0; ni < 8; ni++) {
            int col = bn + wn * 64 + ni * 8 + tg * 2;
            *(float2*)(&C[(size_t)row * D + col]) =
                make_float2(d[mi][ni][0], d[mi][ni][1]);
            *(float2*)(&C[(size_t)(row + 8) * D + col]) =
                make_float2(d[mi][ni][2], d[mi][ni][3]);
        }
    }
}

// ===========================================================================
// Tensor-core flash attention.
// CTA = 128 query rows of one (b,h); 8 warps, each owns 16 rows (m16).
// 64-key tiles, cp.async double-buffered K/V. QK^T uses a 2-MMA tf32 A-split
// (removes Q rounding error); P is rounded to tf32 BEFORE the row-sum so the
// P rounding cancels in O = (P@V)/l. Fully-masked tiles skipped (MASK=-1e6
// underflows exp to 0); vlen==0 processes all tiles -> uniform softmax.
// ===========================================================================
#define BQ 128
#define BKT 64
#define QP 68   // Q smem pitch (bank-conflict-free fragment loads)
#define KP 72   // K/V smem pitch (16B-aligned for cp.async, conflict-free)
#define PP 68   // P smem pitch
#define AT_SMEM_F (BQ * QP + 4 * BKT * KP + 8 * 16 * PP)
#define AT_SMEM_BYTES (AT_SMEM_F * 4)      // 143360

__global__ __launch_bounds__(256, 1) void attn_mma(
    const float* __restrict__ q, const float* __restrict__ k,
    const float* __restrict__ v, const int* __restrict__ valid,
    float* __restrict__ out)
{
    extern __shared__ float sm[];
    float* Qs = sm;                          // [128][QP]
    float* Ks = Qs + BQ * QP;                // 2 x [64][KP]
    float* Vs = Ks + 2 * BKT * KP;           // 2 x [64][KP]
    float* Ps = Vs + 2 * BKT * KP;           // 8 x [16][PP]
    const uint32_t uKs = smem_u32(Ks);
    const uint32_t uVs = smem_u32(Vs);

    const int tid  = threadIdx.x;
    const int wid  = tid >> 5;
    const int lane = tid & 31;
    const int g    = lane >> 2;
    const int tg   = lane & 3;
    const int bh = blockIdx.y;
    const int b  = bh / H;
    const int h  = bh % H;
    const int q0 = blockIdx.x * BQ;
    const int vlen = valid[b];
    const float scale = 0.125f;

    const float* qbase = q + (size_t)b * S * D + (size_t)h * HD;
    const float* kbase = k + (size_t)b * S * D + (size_t)h * HD;
    const float* vbase = v + (size_t)b * S * D + (size_t)h * HD;

    // Load Q tile [128][64] -> Qs
#pragma unroll
    for (int t = 0; t < 8; t++) {
        int idx = tid + t * 256;
        int row = idx >> 4;
        int c   = idx & 15;
        float4 tq = *(const float4*)(qbase + (size_t)(q0 + row) * D + c * 4);
        float* d = &Qs[row * QP + c * 4];
        d[0] = tq.x; d[1] = tq.y; d[2] = tq.z; d[3] = tq.w;
    }

    float o[8][4];
#pragma unroll
    for (int ni = 0; ni < 8; ni++)
#pragma unroll
        for (int c = 0; c < 4; c++) o[ni][c] = 0.f;
    float m0 = -INFINITY, m1 = -INFINITY, l0 = 0.f, l1 = 0.f;

    const int nk = (vlen == 0) ? (S / BKT) : ((vlen + BKT - 1) / BKT);

    // Preload tile 0
    {
#pragma unroll
        for (int t = 0; t < 4; t++) {
            int idx = tid + t * 256;
            int row = idx >> 4;
            int c   = idx & 15;
            uint32_t off = (uint32_t)(row * KP + c * 4) * 4;
            cp_async16(uKs + off, kbase + (size_t)row * D + c * 4);
            cp_async16(uVs + off, vbase + (size_t)row * D + c * 4);
        }
        cp_commit();
    }

    const int r0 = wid * 16;
    float* Pw = Ps + wid * 16 * PP;

    for (int kt = 0; kt < nk; kt++) {
        const int buf = kt & 1;
        const int kr0 = kt * BKT;
        if (kt + 1 < nk) {
            const int nr0 = (kt + 1) * BKT;
            const uint32_t bo = (uint32_t)((buf ^ 1) * BKT * KP) * 4;
#pragma unroll
            for (int t = 0; t < 4; t++) {
                int idx = tid + t * 256;
                int row = idx >> 4;
                int c   = idx & 15;
                uint32_t off = bo + (uint32_t)(row * KP + c * 4) * 4;
                cp_async16(uKs + off, kbase + (size_t)(nr0 + row) * D + c * 4);
                cp_async16(uVs + off, vbase + (size_t)(nr0 + row) * D + c * 4);
            }
            cp_commit();
            asm volatile("cp.async.wait_group 1;" ::: "memory");
        } else {
            asm volatile("cp.async.wait_group 0;" ::: "memory");
        }
        __syncthreads();

        const float* Kb = Ks + buf * BKT * KP;
        const float* Vb = Vs + buf * BKT * KP;

        // ---- S = Q @ K^T (2-MMA tf32 split on Q) ----
        float sc[8][4];
#pragma unroll
        for (int ni = 0; ni < 8; ni++)
#pragma unroll
            for (int c = 0; c < 4; c++) sc[ni][c] = 0.f;

#pragma unroll
        for (int ks = 0; ks < 8; ks++) {
            const int k0 = ks * 8;
            float qf[4];
            qf[0] = Qs[(r0 + g) * QP + k0 + tg];
            qf[1] = Qs[(r0 + g + 8) * QP + k0 + tg];
            qf[2] = Qs[(r0 + g) * QP + k0 + tg + 4];
            qf[3] = Qs[(r0 + g + 8) * QP + k0 + tg + 4];
            uint32_t qh[4], ql[4];
#pragma unroll
            for (int i = 0; i < 4; i++) {
                qh[i] = f2tf32(qf[i]);
                ql[i] = f2tf32(qf[i] - __uint_as_float(qh[i]));
            }
#pragma unroll
            for (int ni = 0; ni < 8; ni++) {
                const float* kr = &Kb[(ni * 8 + g) * KP + k0];
                uint32_t b0 = f2tf32(kr[tg]);
                uint32_t b1 = f2tf32(kr[tg + 4]);
                mma_tf32(sc[ni], qh, b0, b1);
                mma_tf32(sc[ni], ql, b0, b1);
            }
        }

        // ---- mask + scale + online softmax ----
        float mn0 = m0, mn1 = m1;
#pragma unroll
        for (int ni = 0; ni < 8; ni++) {
            int col = kr0 + ni * 8 + 2 * tg;
            bool v0 = col < vlen, v1 = (col + 1) < vlen;
            sc[ni][0] = v0 ? sc[ni][0] * scale : MASK_VALUE;
            sc[ni][1] = v1 ? sc[ni][1] * scale : MASK_VALUE;
            sc[ni][2] = v0 ? sc[ni][2] * scale : MASK_VALUE;
            sc[ni][3] = v1 ? sc[ni][3] * scale : MASK_VALUE;
            mn0 = fmaxf(mn0, fmaxf(sc[ni][0], sc[ni][1]));
            mn1 = fmaxf(mn1, fmaxf(sc[ni][2], sc[ni][3]));
        }
        mn0 = fmaxf(mn0, __shfl_xor_sync(0xffffffffu, mn0, 1));
        mn0 = fmaxf(mn0, __shfl_xor_sync(0xffffffffu, mn0, 2));
        mn1 = fmaxf(mn1, __shfl_xor_sync(0xffffffffu, mn1, 1));
        mn1 = fmaxf(mn1, __shfl_xor_sync(0xffffffffu, mn1, 2));

        float a0 = __expf(m0 - mn0);
        float a1 = __expf(m1 - mn1);
        m0 = mn0; m1 = mn1;

        float rs0 = 0.f, rs1 = 0.f;
#pragma unroll
        for (int ni = 0; ni < 8; ni++) {
            // round p to tf32 BEFORE summing: rounding cancels after /l
            float p0 = __uint_as_float(f2tf32(__expf(sc[ni][0] - mn0)));
            float p1 = __uint_as_float(f2tf32(__expf(sc[ni][1] - mn0)));
            float p2 = __uint_as_float(f2tf32(__expf(sc[ni][2] - mn1)));
            float p3 = __uint_as_float(f2tf32(__expf(sc[ni][3] - mn1)));
            rs0 += p0 + p1;
            rs1 += p2 + p3;
            *(float2*)(&Pw[g * PP + ni * 8 + 2 * tg])       = make_float2(p0, p1);
            *(float2*)(&Pw[(g + 8) * PP + ni * 8 + 2 * tg]) = make_float2(p2, p3);
        }
        rs0 += __shfl_xor_sync(0xffffffffu, rs0, 1);
        rs0 += __shfl_xor_sync(0xffffffffu, rs0, 2);
        rs1 += __shfl_xor_sync(0xffffffffu, rs1, 1);
        rs1 += __shfl_xor_sync(0xffffffffu, rs1, 2);
        l0 = l0 * a0 + rs0;
        l1 = l1 * a1 + rs1;

#pragma unroll
        for (int ni = 0; ni < 8; ni++) {
            o[ni][0] *= a0; o[ni][1] *= a0;
            o[ni][2] *= a1; o[ni][3] *= a1;
        }
        __syncwarp();

        // ---- O += P @ V ----
#pragma unroll
        for (int ks = 0; ks < 8; ks++) {
            const int k0 = ks * 8;
            uint32_t pa[4];
            pa[0] = __float_as_uint(Pw[g * PP + k0 + tg]);
            pa[1] = __float_as_uint(Pw[(g + 8) * PP + k0 + tg]);
            pa[2] = __float_as_uint(Pw[g * PP + k0 + tg + 4]);
            pa[3] = __float_as_uint(Pw[(g + 8) * PP + k0 + tg + 4]);
#pragma unroll
            for (int ni = 0; ni < 8; ni++) {
                uint32_t b0 = f2tf32(Vb[(k0 + tg) * KP + ni * 8 + g]);
                uint32_t b1 = f2tf32(Vb[(k0 + tg + 4) * KP + ni * 8 + g]);
                mma_tf32(o[ni], pa, b0, b1);
            }
        }
        __syncwarp();
        __syncthreads();   // K/V buffer reuse barrier
    }

    // Epilogue
    float inv0 = 1.f / l0, inv1 = 1.f / l1;
    int row0 = q0 + r0 + g;
#pragma unroll
    for (int ni = 0; ni < 8; ni++) {
        int col = h * HD + ni * 8 + 2 * tg;
        *(float2*)(&out[((size_t)b * S + row0) * D + col]) =
            make_float2(o[ni][0] * inv0, o[ni][1] * inv0);
        *(float2*)(&out[((size_t)b * S + row0 + 8) * D + col]) =
            make_float2(o[ni][2] * inv1, o[ni][3] * inv1);
    }
}

// ===========================================================================
// Launch
// ===========================================================================
extern "C" void kernel_launch(void* const* d_in, const int* in_sizes, int n_in,
                              void* d_out, int out_size)
{
    const float* Q  = (const float*)d_in[0];
    const float* K  = (const float*)d_in[1];
    const float* V  = (const float*)d_in[2];
    const int* valid = (const int*)d_in[3];
    const float* Wq = (const float*)d_in[4];
    const float* Wk = (const float*)d_in[5];
    const float* Wv = (const float*)d_in[6];
    const float* Wo = (const float*)d_in[7];
    float* out = (float*)d_out;

    float *gq, *gk, *gv, *ga, *gwt;
    cudaGetSymbolAddress((void**)&gq, g_q);
    cudaGetSymbolAddress((void**)&gk, g_k);
    cudaGetSymbolAddress((void**)&gv, g_v);
    cudaGetSymbolAddress((void**)&ga, g_attn);
    cudaGetSymbolAddress((void**)&gwt, g_wt);
    float* wtq = gwt;
    float* wtk = gwt + (size_t)D * D;
    float* wtv = gwt + (size_t)2 * D * D;
    float* wto = gwt + (size_t)3 * D * D;

    cudaFuncSetAttribute(gemm_tf32, cudaFuncAttributeMaxDynamicSharedMemorySize,
                         GEMM_SMEM_BYTES);
    cudaFuncSetAttribute(attn_mma, cudaFuncAttributeMaxDynamicSharedMemorySize,
                         AT_SMEM_BYTES);

    dim3 tgrid(32, 32), tblk(32, 8);
    transpose_kernel<<<tgrid, tblk>>>(Wq, wtq);
    transpose_kernel<<<tgrid, tblk>>>(Wk, wtk);
    transpose_kernel<<<tgrid, tblk>>>(Wv, wtv);
    transpose_kernel<<<tgrid, tblk>>>(Wo, wto);

    dim3 ggrid(D / 128, (B * S) / 128);  // (8, 32)
    gemm_tf32<<<ggrid, 256, GEMM_SMEM_BYTES>>>(Q, wtq, gq);
    gemm_tf32<<<ggrid, 256, GEMM_SMEM_BYTES>>>(K, wtk, gk);
    gemm_tf32<<<ggrid, 256, GEMM_SMEM_BYTES>>>(V, wtv, gv);

    dim3 agrid(S / BQ, B * H);           // (16, 32)
    attn_mma<<<agrid, 256, AT_SMEM_BYTES>>>(gq, gk, gv, valid, ga);

    gemm_tf32<<<ggrid, 256, GEMM_SMEM_BYTES>>>(ga, wto, out);
}

// round 8
// speedup vs baseline: 4.4376x; 1.1213x over previous
#include <cuda_runtime.h>
#include <math.h>
#include <stdint.h>

// Problem constants
#define B 2
#define S 2048
#define D 1024
#define H 16
#define HD 64
#define MASK_VALUE -1000000.0f
#define BSD (B * S * D)            // 4194304

// Scratch (static device globals — no allocation allowed)
__device__ float g_q[BSD];         // Q-projection output (fp32)
__device__ float g_k[BSD];         // K-projection output (tf32-rounded)
__device__ float g_v[BSD];         // V-projection output (tf32-rounded)
__device__ float g_attn[BSD];      // attention output (tf32-rounded)
__device__ float g_qr[BSD];        // tf32-rounded input activations
__device__ float g_kr[BSD];
__device__ float g_vr[BSD];
__device__ float g_wr[4 * D * D];  // tf32-rounded weights, row-major [K][N]

// ===========================================================================
// Helpers
// ===========================================================================
static __device__ __forceinline__ uint32_t smem_u32(const void* p) {
    uint32_t a;
    asm("{ .reg .u64 t; cvta.to.shared.u64 t, %1; cvt.u32.u64 %0, t; }"
        : "=r"(a) : "l"(p));
    return a;
}
static __device__ __forceinline__ uint32_t f2tf32(float x) {
    uint32_t r;
    asm("cvt.rna.tf32.f32 %0, %1;" : "=r"(r) : "f"(x));
    return r;
}
static __device__ __forceinline__ float rnd_tf32(float x) {
    return __uint_as_float(f2tf32(x));
}
static __device__ __forceinline__ void cp_async16(uint32_t smem, const void* gmem) {
    asm volatile("cp.async.ca.shared.global [%0], [%1], 16;"
                 :: "r"(smem), "l"(gmem) : "memory");
}
static __device__ __forceinline__ void cp_commit() {
    asm volatile("cp.async.commit_group;" ::: "memory");
}
static __device__ __forceinline__ void mma_tf32(
    float d[4], const uint32_t a[4], uint32_t b0, uint32_t b1)
{
    asm volatile(
        "mma.sync.aligned.m16n8k8.row.col.f32.tf32.tf32.f32 "
        "{%0,%1,%2,%3}, {%4,%5,%6,%7}, {%8,%9}, {%0,%1,%2,%3};"
        : "+f"(d[0]), "+f"(d[1]), "+f"(d[2]), "+f"(d[3])
        : "r"(a[0]), "r"(a[1]), "r"(a[2]), "r"(a[3]), "r"(b0), "r"(b1));
}

// ===========================================================================
// Prep: tf32-round activations and weights (elementwise, float4)
// ===========================================================================
__global__ __launch_bounds__(256) void prep_acts(
    const float* __restrict__ Q, const float* __restrict__ K,
    const float* __restrict__ V)
{
    const int z = blockIdx.z;
    const float* src = (z == 0) ? Q : (z == 1) ? K : V;
    float* dst = (z == 0) ? g_qr : (z == 1) ? g_kr : g_vr;
    size_t i = ((size_t)blockIdx.x * 256 + threadIdx.x) * 4;
    float4 t = *(const float4*)(src + i);
    t.x = rnd_tf32(t.x); t.y = rnd_tf32(t.y);
    t.z = rnd_tf32(t.z); t.w = rnd_tf32(t.w);
    *(float4*)(dst + i) = t;
}

__global__ __launch_bounds__(256) void prep_w(
    const float* __restrict__ Wq, const float* __restrict__ Wk,
    const float* __restrict__ Wv, const float* __restrict__ Wo)
{
    const int z = blockIdx.z;
    const float* src = (z == 0) ? Wq : (z == 1) ? Wk : (z == 2) ? Wv : Wo;
    float* dst = g_wr + (size_t)z * D * D;
    size_t i = ((size_t)blockIdx.x * 256 + threadIdx.x) * 4;
    float4 t = *(const float4*)(src + i);
    t.x = rnd_tf32(t.x); t.y = rnd_tf32(t.y);
    t.z = rnd_tf32(t.z); t.w = rnd_tf32(t.w);
    *(float4*)(dst + i) = t;
}

// ===========================================================================
// tf32 mma.sync GEMM core: C[M,N] = A[M,K] @ Bm[K,N], both pre-rounded tf32.
// A row-major, B row-major. 128x128 CTA tile, BK=32, 8 warps (32Mx64N each),
// cp.async double-buffered. No cvt in the hot loop.
// ===========================================================================
#define APITCH 36                    // A smem pitch
#define BP 136                       // B smem pitch (conflict-free frags)
#define ATILE_F (128 * APITCH)       // 4608
#define BTILE_F (32 * BP)            // 4352
#define GEMM_SMEM_BYTES ((2 * ATILE_F + 2 * BTILE_F) * 4)   // 71680

static __device__ __forceinline__ void gemm_load_tile(
    uint32_t sA, uint32_t sB, const float* Ab, const float* Bm,
    int bn, int kc, int tid)
{
#pragma unroll
    for (int t = 0; t < 4; t++) {
        int idx = tid + (t << 8);          // 0..1023
        // A: 128 rows x 32 floats
        int ar = idx >> 3, ac = idx & 7;
        cp_async16(sA + (uint32_t)(ar * APITCH + ac * 4) * 4,
                   Ab + (size_t)ar * D + kc * 32 + ac * 4);
        // B: 32 rows x 128 floats
        int br = idx >> 5, bc = idx & 31;
        cp_async16(sB + (uint32_t)(br * BP + bc * 4) * 4,
                   Bm + (size_t)(kc * 32 + br) * D + bn + bc * 4);
    }
}

static __device__ __forceinline__ void gemm_core(
    const float* __restrict__ A, const float* __restrict__ Bm,
    float* __restrict__ C, bool round_out)
{
    extern __shared__ float smf[];
    float* bufA[2] = { smf,              smf + ATILE_F };
    float* bufB[2] = { smf + 2 * ATILE_F, smf + 2 * ATILE_F + BTILE_F };
    uint32_t uA[2] = { smem_u32(bufA[0]), smem_u32(bufA[1]) };
    uint32_t uB[2] = { smem_u32(bufB[0]), smem_u32(bufB[1]) };

    const int tid = threadIdx.x;
    const int wid = tid >> 5;
    const int lane = tid & 31;
    const int g  = lane >> 2;
    const int tg = lane & 3;
    const int wm = wid & 3;
    const int wn = wid >> 2;

    const int bm = blockIdx.y * 128;
    const int bn = blockIdx.x * 128;
    const float* Ab = A + (size_t)bm * D;

    float d[2][8][4];
#pragma unroll
    for (int mi = 0; mi < 2; mi++)
#pragma unroll
        for (int ni = 0; ni < 8; ni++)
#pragma unroll
            for (int r = 0; r < 4; r++) d[mi][ni][r] = 0.f;

    gemm_load_tile(uA[0], uB[0], Ab, Bm, bn, 0, tid);
    cp_commit();

    for (int kc = 0; kc < D / 32; kc++) {
        const int buf = kc & 1;
        if (kc + 1 < D / 32) {
            gemm_load_tile(uA[buf ^ 1], uB[buf ^ 1], Ab, Bm, bn, kc + 1, tid);
            cp_commit();
            asm volatile("cp.async.wait_group 1;" ::: "memory");
        } else {
            asm volatile("cp.async.wait_group 0;" ::: "memory");
        }
        __syncthreads();

        const float* As = bufA[buf];
        const float* Bs = bufB[buf];
#pragma unroll
        for (int ks = 0; ks < 4; ks++) {
            const int k0 = ks * 8;
            uint32_t af[2][4];
#pragma unroll
            for (int mi = 0; mi < 2; mi++) {
                int r = wm * 32 + mi * 16 + g;
                af[mi][0] = __float_as_uint(As[r * APITCH + k0 + tg]);
                af[mi][1] = __float_as_uint(As[(r + 8) * APITCH + k0 + tg]);
                af[mi][2] = __float_as_uint(As[r * APITCH + k0 + tg + 4]);
                af[mi][3] = __float_as_uint(As[(r + 8) * APITCH + k0 + tg + 4]);
            }
#pragma unroll
            for (int ni = 0; ni < 8; ni++) {
                int col = wn * 64 + ni * 8 + g;
                uint32_t b0 = __float_as_uint(Bs[(k0 + tg) * BP + col]);
                uint32_t b1 = __float_as_uint(Bs[(k0 + tg + 4) * BP + col]);
#pragma unroll
                for (int mi = 0; mi < 2; mi++)
                    mma_tf32(d[mi][ni], af[mi], b0, b1);
            }
        }
        __syncthreads();
    }

#pragma unroll
    for (int mi = 0; mi < 2; mi++) {
        int row = bm + wm * 32 + mi * 16 + g;
#pragma unroll
        for (int ni = 0; ni < 8; ni++) {
            int col = bn + wn * 64 + ni * 8 + tg * 2;
            float v0 = d[mi][ni][0], v1 = d[mi][ni][1];
            float v2 = d[mi][ni][2], v3 = d[mi][ni][3];
            if (round_out) {
                v0 = rnd_tf32(v0); v1 = rnd_tf32(v1);
                v2 = rnd_tf32(v2); v3 = rnd_tf32(v3);
            }
            *(float2*)(&C[(size_t)row * D + col]) = make_float2(v0, v1);
            *(float2*)(&C[(size_t)(row + 8) * D + col]) = make_float2(v2, v3);
        }
    }
}

// Fused Q/K/V projections: grid.z selects which. K/V outputs tf32-rounded
// (they feed attention's tensor ops; rounding here == rounding at use).
__global__ __launch_bounds__(256, 2) void gemm_qkv()
{
    const int z = blockIdx.z;
    const float* A = (z == 0) ? g_qr : (z == 1) ? g_kr : g_vr;
    const float* Bm = g_wr + (size_t)z * D * D;
    float* C = (z == 0) ? g_q : (z == 1) ? g_k : g_v;
    gemm_core(A, Bm, C, z > 0);
}

// Output projection: A = g_attn (pre-rounded by attention epilogue).
__global__ __launch_bounds__(256, 2) void gemm_out(float* __restrict__ C)
{
    gemm_core(g_attn, g_wr + (size_t)3 * D * D, C, false);
}

// ===========================================================================
// Tensor-core flash attention. CTA = 128 query rows of one (b,h); 8 warps.
// K/V arrive pre-rounded tf32 (no cvt in loop). QK^T uses 2-MMA tf32 split
// on Q; P rounded to tf32 before row-sum so rounding cancels in O = PV/l.
// Fully-masked tiles skipped (MASK=-1e6 underflows exp to 0); vlen==0
// processes all tiles -> uniform softmax. Output rounded to tf32 for gemm_out.
// ===========================================================================
#define BQ 128
#define BKT 64
#define QP 68
#define KP 72
#define PP 68
#define AT_SMEM_F (BQ * QP + 4 * BKT * KP + 8 * 16 * PP)
#define AT_SMEM_BYTES (AT_SMEM_F * 4)      // 143360

__global__ __launch_bounds__(256, 1) void attn_mma(
    const int* __restrict__ valid, float* __restrict__ out)
{
    extern __shared__ float sm[];
    float* Qs = sm;                          // [128][QP]
    float* Ks = Qs + BQ * QP;                // 2 x [64][KP]
    float* Vs = Ks + 2 * BKT * KP;           // 2 x [64][KP]
    float* Ps = Vs + 2 * BKT * KP;           // 8 x [16][PP]
    const uint32_t uKs = smem_u32(Ks);
    const uint32_t uVs = smem_u32(Vs);

    const int tid  = threadIdx.x;
    const int wid  = tid >> 5;
    const int lane = tid & 31;
    const int g    = lane >> 2;
    const int tg   = lane & 3;
    const int bh = blockIdx.y;
    const int b  = bh / H;
    const int h  = bh % H;
    const int q0 = blockIdx.x * BQ;
    const int vlen = valid[b];
    const float scale = 0.125f;

    const float* qbase = g_q + (size_t)b * S * D + (size_t)h * HD;
    const float* kbase = g_k + (size_t)b * S * D + (size_t)h * HD;
    const float* vbase = g_v + (size_t)b * S * D + (size_t)h * HD;

#pragma unroll
    for (int t = 0; t < 8; t++) {
        int idx = tid + t * 256;
        int row = idx >> 4;
        int c   = idx & 15;
        float4 tq = *(const float4*)(qbase + (size_t)(q0 + row) * D + c * 4);
        float* dq = &Qs[row * QP + c * 4];
        dq[0] = tq.x; dq[1] = tq.y; dq[2] = tq.z; dq[3] = tq.w;
    }

    float o[8][4];
#pragma unroll
    for (int ni = 0; ni < 8; ni++)
#pragma unroll
        for (int c = 0; c < 4; c++) o[ni][c] = 0.f;
    float m0 = -INFINITY, m1 = -INFINITY, l0 = 0.f, l1 = 0.f;

    const int nk = (vlen == 0) ? (S / BKT) : ((vlen + BKT - 1) / BKT);

    {
#pragma unroll
        for (int t = 0; t < 4; t++) {
            int idx = tid + t * 256;
            int row = idx >> 4;
            int c   = idx & 15;
            uint32_t off = (uint32_t)(row * KP + c * 4) * 4;
            cp_async16(uKs + off, kbase + (size_t)row * D + c * 4);
            cp_async16(uVs + off, vbase + (size_t)row * D + c * 4);
        }
        cp_commit();
    }

    const int r0 = wid * 16;
    float* Pw = Ps + wid * 16 * PP;

    for (int kt = 0; kt < nk; kt++) {
        const int buf = kt & 1;
        const int kr0 = kt * BKT;
        if (kt + 1 < nk) {
            const int nr0 = (kt + 1) * BKT;
            const uint32_t bo = (uint32_t)((buf ^ 1) * BKT * KP) * 4;
#pragma unroll
            for (int t = 0; t < 4; t++) {
                int idx = tid + t * 256;
                int row = idx >> 4;
                int c   = idx & 15;
                uint32_t off = bo + (uint32_t)(row * KP + c * 4) * 4;
                cp_async16(uKs + off, kbase + (size_t)(nr0 + row) * D + c * 4);
                cp_async16(uVs + off, vbase + (size_t)(nr0 + row) * D + c * 4);
            }
            cp_commit();
            asm volatile("cp.async.wait_group 1;" ::: "memory");
        } else {
            asm volatile("cp.async.wait_group 0;" ::: "memory");
        }
        __syncthreads();

        const float* Kb = Ks + buf * BKT * KP;
        const float* Vb = Vs + buf * BKT * KP;

        // ---- S = Q @ K^T (2-MMA tf32 split on Q; K pre-rounded) ----
        float sc[8][4];
#pragma unroll
        for (int ni = 0; ni < 8; ni++)
#pragma unroll
            for (int c = 0; c < 4; c++) sc[ni][c] = 0.f;

#pragma unroll
        for (int ks = 0; ks < 8; ks++) {
            const int k0 = ks * 8;
            float qf[4];
            qf[0] = Qs[(r0 + g) * QP + k0 + tg];
            qf[1] = Qs[(r0 + g + 8) * QP + k0 + tg];
            qf[2] = Qs[(r0 + g) * QP + k0 + tg + 4];
            qf[3] = Qs[(r0 + g + 8) * QP + k0 + tg + 4];
            uint32_t qh[4], ql[4];
#pragma unroll
            for (int i = 0; i < 4; i++) {
                qh[i] = f2tf32(qf[i]);
                ql[i] = f2tf32(qf[i] - __uint_as_float(qh[i]));
            }
#pragma unroll
            for (int ni = 0; ni < 8; ni++) {
                const float* kr = &Kb[(ni * 8 + g) * KP + k0];
                uint32_t b0 = __float_as_uint(kr[tg]);
                uint32_t b1 = __float_as_uint(kr[tg + 4]);
                mma_tf32(sc[ni], qh, b0, b1);
                mma_tf32(sc[ni], ql, b0, b1);
            }
        }

        // ---- mask + scale + online softmax ----
        float mn0 = m0, mn1 = m1;
#pragma unroll
        for (int ni = 0; ni < 8; ni++) {
            int col = kr0 + ni * 8 + 2 * tg;
            bool v0 = col < vlen, v1 = (col + 1) < vlen;
            sc[ni][0] = v0 ? sc[ni][0] * scale : MASK_VALUE;
            sc[ni][1] = v1 ? sc[ni][1] * scale : MASK_VALUE;
            sc[ni][2] = v0 ? sc[ni][2] * scale : MASK_VALUE;
            sc[ni][3] = v1 ? sc[ni][3] * scale : MASK_VALUE;
            mn0 = fmaxf(mn0, fmaxf(sc[ni][0], sc[ni][1]));
            mn1 = fmaxf(mn1, fmaxf(sc[ni][2], sc[ni][3]));
        }
        mn0 = fmaxf(mn0, __shfl_xor_sync(0xffffffffu, mn0, 1));
        mn0 = fmaxf(mn0, __shfl_xor_sync(0xffffffffu, mn0, 2));
        mn1 = fmaxf(mn1, __shfl_xor_sync(0xffffffffu, mn1, 1));
        mn1 = fmaxf(mn1, __shfl_xor_sync(0xffffffffu, mn1, 2));

        float a0 = __expf(m0 - mn0);
        float a1 = __expf(m1 - mn1);
        m0 = mn0; m1 = mn1;

        float rs0 = 0.f, rs1 = 0.f;
#pragma unroll
        for (int ni = 0; ni < 8; ni++) {
            float p0 = rnd_tf32(__expf(sc[ni][0] - mn0));
            float p1 = rnd_tf32(__expf(sc[ni][1] - mn0));
            float p2 = rnd_tf32(__expf(sc[ni][2] - mn1));
            float p3 = rnd_tf32(__expf(sc[ni][3] - mn1));
            rs0 += p0 + p1;
            rs1 += p2 + p3;
            *(float2*)(&Pw[g * PP + ni * 8 + 2 * tg])       = make_float2(p0, p1);
            *(float2*)(&Pw[(g + 8) * PP + ni * 8 + 2 * tg]) = make_float2(p2, p3);
        }
        rs0 += __shfl_xor_sync(0xffffffffu, rs0, 1);
        rs0 += __shfl_xor_sync(0xffffffffu, rs0, 2);
        rs1 += __shfl_xor_sync(0xffffffffu, rs1, 1);
        rs1 += __shfl_xor_sync(0xffffffffu, rs1, 2);
        l0 = l0 * a0 + rs0;
        l1 = l1 * a1 + rs1;

#pragma unroll
        for (int ni = 0; ni < 8; ni++) {
            o[ni][0] *= a0; o[ni][1] *= a0;
            o[ni][2] *= a1; o[ni][3] *= a1;
        }
        __syncwarp();

        // ---- O += P @ V (both pre-rounded tf32) ----
#pragma unroll
        for (int ks = 0; ks < 8; ks++) {
            const int k0 = ks * 8;
            uint32_t pa[4];
            pa[0] = __float_as_uint(Pw[g * PP + k0 + tg]);
            pa[1] = __float_as_uint(Pw[(g + 8) * PP + k0 + tg]);
            pa[2] = __float_as_uint(Pw[g * PP + k0 + tg + 4]);
            pa[3] = __float_as_uint(Pw[(g + 8) * PP + k0 + tg + 4]);
#pragma unroll
            for (int ni = 0; ni < 8; ni++) {
                uint32_t b0 = __float_as_uint(Vb[(k0 + tg) * KP + ni * 8 + g]);
                uint32_t b1 = __float_as_uint(Vb[(k0 + tg + 4) * KP + ni * 8 + g]);
                mma_tf32(o[ni], pa, b0, b1);
            }
        }
        __syncwarp();
        __syncthreads();
    }

    // Epilogue: normalize + round to tf32 (feeds gemm_out's raw loads)
    float inv0 = 1.f / l0, inv1 = 1.f / l1;
    int row0 = q0 + r0 + g;
#pragma unroll
    for (int ni = 0; ni < 8; ni++) {
        int col = h * HD + ni * 8 + 2 * tg;
        *(float2*)(&out[((size_t)b * S + row0) * D + col]) =
            make_float2(rnd_tf32(o[ni][0] * inv0), rnd_tf32(o[ni][1] * inv0));
        *(float2*)(&out[((size_t)b * S + row0 + 8) * D + col]) =
            make_float2(rnd_tf32(o[ni][2] * inv1), rnd_tf32(o[ni][3] * inv1));
    }
}

// ===========================================================================
// Launch
// ===========================================================================
extern "C" void kernel_launch(void* const* d_in, const int* in_sizes, int n_in,
                              void* d_out, int out_size)
{
    const float* Q  = (const float*)d_in[0];
    const float* K  = (const float*)d_in[1];
    const float* V  = (const float*)d_in[2];
    const int* valid = (const int*)d_in[3];
    const float* Wq = (const float*)d_in[4];
    const float* Wk = (const float*)d_in[5];
    const float* Wv = (const float*)d_in[6];
    const float* Wo = (const float*)d_in[7];
    float* out = (float*)d_out;

    float* ga;
    cudaGetSymbolAddress((void**)&ga, g_attn);

    cudaFuncSetAttribute(gemm_qkv, cudaFuncAttributeMaxDynamicSharedMemorySize,
                         GEMM_SMEM_BYTES);
    cudaFuncSetAttribute(gemm_out, cudaFuncAttributeMaxDynamicSharedMemorySize,
                         GEMM_SMEM_BYTES);
    cudaFuncSetAttribute(attn_mma, cudaFuncAttributeMaxDynamicSharedMemorySize,
                         AT_SMEM_BYTES);

    // Prep: round activations and weights to tf32
    prep_acts<<<dim3(BSD / 4 / 256, 1, 3), 256>>>(Q, K, V);
    prep_w<<<dim3(D * D / 4 / 256, 1, 4), 256>>>(Wq, Wk, Wv, Wo);

    // Fused Q/K/V projections (one wave: 768 CTAs)
    gemm_qkv<<<dim3(D / 128, (B * S) / 128, 3), 256, GEMM_SMEM_BYTES>>>();

    // Attention
    attn_mma<<<dim3(S / BQ, B * H), 256, AT_SMEM_BYTES>>>(valid, ga);

    // Output projection
    gemm_out<<<dim3(D / 128, (B * S) / 128), 256, GEMM_SMEM_BYTES>>>(out);
}